// round 7
// baseline (speedup 1.0000x reference)
#include <cuda_runtime.h>
#include <cstdint>

static constexpr int K_TOTAL = 1280, N_TOTAL = 1280;
static constexpr int BM = 128, BN = 256;
static constexpr int SLICES32 = 40, SLICES64 = 20;
static constexpr int NTILES = 5, MTILES = 512;
static constexpr int GRID = NTILES * MTILES;  // 2560
static constexpr int THREADS = 512;

// smem (bytes): A 2*32K | B 2*64K | B2 2*2K | WU 4K | DN 2K
static constexpr int A_ST = 32768, B_ST = 65536, B2_ST = 2048;
static constexpr int OFF_A = 0;
static constexpr int OFF_B = 65536;
static constexpr int OFF_B2 = 196608;
static constexpr int OFF_WU = 200704;
static constexpr int OFF_DN = 204800;
static constexpr int SMEM_BYTES = 206848;

// W fragments, per 32-k slice block of 8192 floats:
// ((((pair)*4+ks)*32 + gid*4 + tig)*4 + nfo*2 + kh), pair = n16-group 0..15
__device__ __align__(16) float g_Wfrag[NTILES * SLICES32 * 8192];
// Wd fragments: [lora][slice32][(ks*32+lane)*2 + kh]
__device__ __align__(16) float g_Wdfrag[50 * SLICES32 * 256];

__device__ __forceinline__ uint32_t smem_u32(const void* p) {
    uint32_t a;
    asm("{ .reg .u64 t; cvta.to.shared.u64 t, %1; cvt.u32.u64 %0, t; }" : "=r"(a) : "l"(p));
    return a;
}
__device__ __forceinline__ uint32_t rna(float f) {
    uint32_t b;
    asm("cvt.rna.tf32.f32 %0, %1;" : "=r"(b) : "f"(f));
    return b;
}
__device__ __forceinline__ void mma8(float* c, const uint32_t* a, uint32_t b0, uint32_t b1) {
    asm volatile(
        "mma.sync.aligned.m16n8k8.row.col.f32.tf32.tf32.f32 "
        "{%0,%1,%2,%3}, {%4,%5,%6,%7}, {%8,%9}, {%0,%1,%2,%3};"
        : "+f"(c[0]), "+f"(c[1]), "+f"(c[2]), "+f"(c[3])
        : "r"(a[0]), "r"(a[1]), "r"(a[2]), "r"(a[3]), "r"(b0), "r"(b1));
}
#define CP16(d, s) asm volatile("cp.async.cg.shared.global [%0], [%1], 16;" :: "r"(d), "l"(s))
#define CP4(d, s)  asm volatile("cp.async.ca.shared.global [%0], [%1], 4;"  :: "r"(d), "l"(s))
#define CP_COMMIT() asm volatile("cp.async.commit_group;")
#define CP_WAIT0()  asm volatile("cp.async.wait_group 0;" ::: "memory")

// ---------------- prepass (identical layout to R6)
__global__ void prep_kernel(const float* __restrict__ W, const float* __restrict__ Wd) {
    int i = blockIdx.x * blockDim.x + threadIdx.x;
    const int NW = N_TOTAL * K_TOTAL;
    if (i < NW) {
        int n = i / K_TOTAL, k = i % K_TOTAL;
        int ntile = n >> 8, nn = n & 255;
        int pair = nn >> 4, nf8 = (nn >> 3) & 1, gid = nn & 7;  // pair 0..15, nfo = nf8
        int slice = k >> 5, ks = (k >> 3) & 3, kh = (k >> 2) & 1, tig = k & 3;
        int off = (ntile * SLICES32 + slice) * 8192 +
                  (((pair * 4 + ks) * 32 + gid * 4 + tig) * 4 + nf8 * 2 + kh);
        g_Wfrag[off] = __uint_as_float(rna(W[i]));
    } else if (i < NW + 50 * K_TOTAL * 8) {
        int j = i - NW;
        int gid = j & 7, t = j >> 3, k = t % K_TOTAL, l = t / K_TOTAL;
        float v = 0.f;
        if (gid < 4) v = __uint_as_float(rna(Wd[(l * 4 + gid) * K_TOTAL + k]));
        int slice = k >> 5, ks = (k >> 3) & 3, kh = (k >> 2) & 1, tig = k & 3;
        g_Wdfrag[(l * SLICES32 + slice) * 256 + (ks * 32 + gid * 4 + tig) * 2 + kh] = v;
    }
}

// ---------------- main fused kernel: 512 threads, 16 warps, warp tile 64x32
__global__ void __launch_bounds__(THREADS, 1)
lora_gemm(const float* __restrict__ x, const int* __restrict__ lora_id,
          const float* __restrict__ Wu, float* __restrict__ out) {
    extern __shared__ char smem[];
    const uint32_t sb = smem_u32(smem);
    const int tid = threadIdx.x, lane = tid & 31, wid = tid >> 5;
    const int bid = blockIdx.x;
    const int ntile = bid % NTILES, mtile = bid / NTILES;
    const int m0 = mtile * BM, nb = ntile * BN;

    const int id = lora_id[m0 >> 12];
    const int idx = (id >= 0) ? ((id >> 2) > 49 ? 49 : (id >> 2)) : 0;
    const float coeff = (id >= 0) ? 1.f : 0.f;

    // stage Wu tile (fp32), 256 float4
    if (tid < 256) {
        const float4* wusrc = (const float4*)Wu + (size_t)idx * N_TOTAL;
        ((float4*)(smem + OFF_WU))[tid] = wusrc[nb + tid];
    }

    const int gid = lane >> 2, tig = lane & 3;
    const int wr = wid >> 3, wc = wid & 7;   // 2 x 8 warp grid

    // producer indexing: row pr (0..127), k-quarter pq (16 floats)
    const int pr = tid >> 2, pq = tid & 3;
    const float* xrow = x + (size_t)(m0 + pr) * K_TOTAL + pq * 16;
    const int mfg = pr >> 4, agid = pr & 7, ah = (pr >> 3) & 1;
    const int sA = (agid >> 1) & 3;
    const int pph = pq >> 1;                 // which 32-k phase this thread fills
    const int pks = (pq & 1) * 2;            // base ks within phase
    const uint32_t asts = sb + OFF_A + pph * 16384 +
                          ((mfg * 4 * 32 + agid * 4) << 4) + ah * 4;

    // consumer bases
    const uint32_t acons = sb + OFF_A + ((wr * 16 * 32) << 4) +
                           ((gid * 4 + (tig ^ ((gid >> 1) & 3))) << 4);
    const uint32_t bcons = sb + OFF_B + wc * 4096 + (lane << 4);
    const uint32_t b2cons = sb + OFF_B2 + lane * 8;

    const float* wsrc = g_Wfrag + (size_t)ntile * SLICES32 * 8192;
    const float* wdsrc = g_Wdfrag + (size_t)idx * SLICES32 * 256;

    float acc[4][4][4];
    float accL[4][4];
    #pragma unroll
    for (int a = 0; a < 4; ++a) {
        #pragma unroll
        for (int b = 0; b < 4; ++b)
            acc[a][b][0] = acc[a][b][1] = acc[a][b][2] = acc[a][b][3] = 0.f;
        accL[a][0] = accL[a][1] = accL[a][2] = accL[a][3] = 0.f;
    }

    // ---- preload slice64 0 into stage 0
    {
        #pragma unroll
        for (int c = 0; c < 8; ++c)
            CP16(sb + OFF_B + tid * 128 + c * 16, wsrc + tid * 32 + c * 4);
        CP4(sb + OFF_B2 + tid * 4, wdsrc + tid);
        CP_COMMIT();
        #pragma unroll
        for (int j = 0; j < 4; ++j) {
            float4 v = ((const float4*)xrow)[j];
            uint32_t r0 = rna(v.x), r1 = rna(v.y), r2 = rna(v.z), r3 = rna(v.w);
            uint32_t ab = asts + (((pks + (j >> 1)) * 32) << 4) + (j & 1) * 8;
            asm volatile("st.shared.b32 [%0], %1;" :: "r"(ab + ((0 ^ sA) << 4)), "r"(r0));
            asm volatile("st.shared.b32 [%0], %1;" :: "r"(ab + ((1 ^ sA) << 4)), "r"(r1));
            asm volatile("st.shared.b32 [%0], %1;" :: "r"(ab + ((2 ^ sA) << 4)), "r"(r2));
            asm volatile("st.shared.b32 [%0], %1;" :: "r"(ab + ((3 ^ sA) << 4)), "r"(r3));
        }
        CP_WAIT0();
        __syncthreads();
    }

    // ---- main loop over 64-k slices
    #pragma unroll 1
    for (int s = 0; s < SLICES64; ++s) {
        const int cur = s & 1, nxt = cur ^ 1;
        const bool pf = (s + 1) < SLICES64;
        float4 xv[4];
        if (pf) {
            const float* wp = wsrc + (size_t)(s + 1) * 16384;
            #pragma unroll
            for (int c = 0; c < 8; ++c)
                CP16(sb + OFF_B + nxt * B_ST + tid * 128 + c * 16, wp + tid * 32 + c * 4);
            CP4(sb + OFF_B2 + nxt * B2_ST + tid * 4, wdsrc + (s + 1) * 512 + tid);
            CP_COMMIT();
            const float* xp = xrow + (s + 1) * 64;
            #pragma unroll
            for (int j = 0; j < 4; ++j) xv[j] = ((const float4*)xp)[j];
        }
        #pragma unroll
        for (int ph = 0; ph < 2; ++ph) {
            const uint32_t ab0 = acons + cur * A_ST + ph * 16384;
            const uint32_t bb0 = bcons + cur * B_ST + ph * 32768;
            const uint32_t b20 = b2cons + cur * B2_ST + ph * 1024;
            #pragma unroll
            for (int ksl = 0; ksl < 4; ++ksl) {
                uint32_t a[4][4];
                #pragma unroll
                for (int mf = 0; mf < 4; ++mf)
                    asm volatile("ld.shared.v4.b32 {%0,%1,%2,%3}, [%4];"
                                 : "=r"(a[mf][0]), "=r"(a[mf][1]), "=r"(a[mf][2]), "=r"(a[mf][3])
                                 : "r"(ab0 + (((mf * 4 + ksl) * 32) << 4)));
                #pragma unroll
                for (int nfp = 0; nfp < 2; ++nfp) {
                    uint32_t b[4];
                    asm volatile("ld.shared.v4.b32 {%0,%1,%2,%3}, [%4];"
                                 : "=r"(b[0]), "=r"(b[1]), "=r"(b[2]), "=r"(b[3])
                                 : "r"(bb0 + (((nfp * 4 + ksl) * 32) << 4)));
                    #pragma unroll
                    for (int mf = 0; mf < 4; ++mf) {
                        mma8(acc[mf][2 * nfp], a[mf], b[0], b[1]);
                        mma8(acc[mf][2 * nfp + 1], a[mf], b[2], b[3]);
                    }
                }
                if (wc == 0) {
                    uint32_t b2[2];
                    asm volatile("ld.shared.v2.b32 {%0,%1}, [%2];"
                                 : "=r"(b2[0]), "=r"(b2[1]) : "r"(b20 + ksl * 256));
                    #pragma unroll
                    for (int mf = 0; mf < 4; ++mf) mma8(accL[mf], a[mf], b2[0], b2[1]);
                }
            }
        }
        if (pf) {
            #pragma unroll
            for (int j = 0; j < 4; ++j) {
                uint32_t r0 = rna(xv[j].x), r1 = rna(xv[j].y),
                         r2 = rna(xv[j].z), r3 = rna(xv[j].w);
                uint32_t ab = asts + nxt * A_ST + (((pks + (j >> 1)) * 32) << 4) + (j & 1) * 8;
                asm volatile("st.shared.b32 [%0], %1;" :: "r"(ab + ((0 ^ sA) << 4)), "r"(r0));
                asm volatile("st.shared.b32 [%0], %1;" :: "r"(ab + ((1 ^ sA) << 4)), "r"(r1));
                asm volatile("st.shared.b32 [%0], %1;" :: "r"(ab + ((2 ^ sA) << 4)), "r"(r2));
                asm volatile("st.shared.b32 [%0], %1;" :: "r"(ab + ((3 ^ sA) << 4)), "r"(r3));
            }
        }
        CP_WAIT0();
        __syncthreads();
    }

    // ---- epilogue: stage lora-down, fused add + store
    float* dns = (float*)(smem + OFF_DN);
    if (wc == 0 && tig < 2) {
        #pragma unroll
        for (int mf = 0; mf < 4; ++mf) {
            int mlo = wr * 64 + mf * 16 + gid, mhi = mlo + 8;
            dns[mlo * 4 + 2 * tig] = accL[mf][0] * coeff;
            dns[mlo * 4 + 2 * tig + 1] = accL[mf][1] * coeff;
            dns[mhi * 4 + 2 * tig] = accL[mf][2] * coeff;
            dns[mhi * 4 + 2 * tig + 1] = accL[mf][3] * coeff;
        }
    }
    __syncthreads();

    const float4* wus = (const float4*)(smem + OFF_WU);
    #pragma unroll
    for (int mf = 0; mf < 4; ++mf) {
        int mlo = wr * 64 + mf * 16 + gid, mhi = mlo + 8;
        float4 dlo = ((const float4*)dns)[mlo];
        float4 dhi = ((const float4*)dns)[mhi];
        float* olo = out + (size_t)(m0 + mlo) * N_TOTAL + nb;
        float* ohi = out + (size_t)(m0 + mhi) * N_TOTAL + nb;
        #pragma unroll
        for (int nf = 0; nf < 4; ++nf) {
            int n = wc * 32 + nf * 8 + 2 * tig;
            float4 w0 = wus[n], w1 = wus[n + 1];
            float2 vlo, vhi;
            vlo.x = acc[mf][nf][0] + dlo.x * w0.x + dlo.y * w0.y + dlo.z * w0.z + dlo.w * w0.w;
            vlo.y = acc[mf][nf][1] + dlo.x * w1.x + dlo.y * w1.y + dlo.z * w1.z + dlo.w * w1.w;
            vhi.x = acc[mf][nf][2] + dhi.x * w0.x + dhi.y * w0.y + dhi.z * w0.z + dhi.w * w0.w;
            vhi.y = acc[mf][nf][3] + dhi.x * w1.x + dhi.y * w1.y + dhi.z * w1.z + dhi.w * w1.w;
            *(float2*)(olo + n) = vlo;
            *(float2*)(ohi + n) = vhi;
        }
    }
}

extern "C" void kernel_launch(void* const* d_in, const int* in_sizes, int n_in,
                              void* d_out, int out_size) {
    const float* x = (const float*)d_in[0];
    const int* lid = (const int*)d_in[1];
    const float* W = (const float*)d_in[2];
    const float* Wd = (const float*)d_in[3];
    const float* Wu = (const float*)d_in[4];
    float* out = (float*)d_out;

    cudaFuncSetAttribute(lora_gemm, cudaFuncAttributeMaxDynamicSharedMemorySize, SMEM_BYTES);
    int total = N_TOTAL * K_TOTAL + 50 * K_TOTAL * 8;
    prep_kernel<<<(total + 255) / 256, 256>>>(W, Wd);
    lora_gemm<<<GRID, THREADS, SMEM_BYTES>>>(x, lid, Wu, out);
}

// round 8
// speedup vs baseline: 1.5695x; 1.5695x over previous
#include <cuda_runtime.h>
#include <cstdint>

static constexpr int K_TOTAL = 1280, N_TOTAL = 1280;
static constexpr int BM = 128, BN = 256;
static constexpr int SLICES = 40;              // 32-k slices
static constexpr int NTILES = 5, MTILES = 512;
static constexpr int GRID = NTILES * MTILES;   // 2560
static constexpr int THREADS = 256;

// smem layout (bytes), 3 stages
static constexpr int A_STG = 18432;   // 128 rows * 144B (32 floats + 16B pad)
static constexpr int B_STG = 32768;   // 8192 floats
static constexpr int B2_STG = 1024;   // 256 floats
static constexpr int OFF_A = 0;                 // 3*18432 = 55296
static constexpr int OFF_B = 55296;             // 3*32768 = 98304
static constexpr int OFF_B2 = 153600;           // 3*1024 = 3072
static constexpr int OFF_WU = 156672;           // 4096
static constexpr int OFF_DN = 160768;           // 2048
static constexpr int OFF_BAR = 162816;          // 3 mbarriers
static constexpr int SMEM_BYTES = 163840;
static constexpr unsigned TX_BYTES = 16384u + 32768u + 1024u;  // A + B + B2

// W fragments, per 32-k slice block of 8192 floats (true mma tf32 convention):
// ((((wc*4+nfp)*4+ks)*32 + gid*4 + tig)*4 + nfo*2 + kh), k = ks*8 + kh*4 + tig
__device__ __align__(16) float g_Wfrag[NTILES * SLICES * 8192];
// Wd fragments: [lora][slice32][(ks*32+lane)*2 + kh]
__device__ __align__(16) float g_Wdfrag[50 * SLICES * 256];

__device__ __forceinline__ uint32_t smem_u32(const void* p) {
    uint32_t a;
    asm("{ .reg .u64 t; cvta.to.shared.u64 t, %1; cvt.u32.u64 %0, t; }" : "=r"(a) : "l"(p));
    return a;
}
__device__ __forceinline__ uint32_t rna(float f) {
    uint32_t b;
    asm("cvt.rna.tf32.f32 %0, %1;" : "=r"(b) : "f"(f));
    return b;
}
__device__ __forceinline__ void mma8(float* c, const uint32_t* a, uint32_t b0, uint32_t b1) {
    asm volatile(
        "mma.sync.aligned.m16n8k8.row.col.f32.tf32.tf32.f32 "
        "{%0,%1,%2,%3}, {%4,%5,%6,%7}, {%8,%9}, {%0,%1,%2,%3};"
        : "+f"(c[0]), "+f"(c[1]), "+f"(c[2]), "+f"(c[3])
        : "r"(a[0]), "r"(a[1]), "r"(a[2]), "r"(a[3]), "r"(b0), "r"(b1));
}
__device__ __forceinline__ void bulk_cp(uint32_t dst, const void* src, uint32_t bytes, uint32_t mb) {
    asm volatile(
        "cp.async.bulk.shared::cta.global.mbarrier::complete_tx::bytes [%0], [%1], %2, [%3];"
        :: "r"(dst), "l"(src), "r"(bytes), "r"(mb) : "memory");
}
#define MBAR_INIT(a, c) \
    asm volatile("mbarrier.init.shared.b64 [%0], %1;" :: "r"((uint32_t)(a)), "r"((uint32_t)(c)) : "memory")
#define MBAR_EXPECT(a, tx) \
    asm volatile("mbarrier.arrive.expect_tx.shared.b64 _, [%0], %1;" :: "r"((uint32_t)(a)), "r"((uint32_t)(tx)) : "memory")
#define MBAR_WAIT(a, ph) do { \
    uint32_t _m = (uint32_t)(a), _p = (uint32_t)(ph), _d; \
    asm volatile("{ .reg .pred p; mbarrier.try_wait.parity.acquire.cta.shared::cta.b64 p, [%1], %2; selp.b32 %0, 1, 0, p; }" \
        : "=r"(_d) : "r"(_m), "r"(_p) : "memory"); \
    if (!_d) { \
        asm volatile("{ .reg .pred P1;\nWL_%=: mbarrier.try_wait.parity.acquire.cta.shared::cta.b64 P1, [%0], %1, 0x989680;\n@P1 bra.uni WD_%=;\nbra.uni WL_%=;\nWD_%=: }" \
            :: "r"(_m), "r"(_p) : "memory"); \
    } \
} while (0)

// ---------------- prepass (identical fragment layout to R6)
__global__ void prep_kernel(const float* __restrict__ W, const float* __restrict__ Wd) {
    int i = blockIdx.x * blockDim.x + threadIdx.x;
    const int NW = N_TOTAL * K_TOTAL;
    if (i < NW) {
        int n = i / K_TOTAL, k = i % K_TOTAL;
        int ntile = n >> 8, nn = n & 255;
        int wc = nn >> 6, nf = (nn >> 3) & 7, gid = nn & 7;
        int nfp = nf >> 1, nfo = nf & 1;
        int slice = k >> 5, ks = (k >> 3) & 3, kh = (k >> 2) & 1, tig = k & 3;
        int off = (ntile * SLICES + slice) * 8192 +
                  ((((wc * 4 + nfp) * 4 + ks) * 32 + gid * 4 + tig) * 4 + nfo * 2 + kh);
        g_Wfrag[off] = __uint_as_float(rna(W[i]));
    } else if (i < NW + 50 * K_TOTAL * 8) {
        int j = i - NW;
        int gid = j & 7, t = j >> 3, k = t % K_TOTAL, l = t / K_TOTAL;
        float v = 0.f;
        if (gid < 4) v = __uint_as_float(rna(Wd[(l * 4 + gid) * K_TOTAL + k]));
        int slice = k >> 5, ks = (k >> 3) & 3, kh = (k >> 2) & 1, tig = k & 3;
        g_Wdfrag[(l * SLICES + slice) * 256 + (ks * 32 + gid * 4 + tig) * 2 + kh] = v;
    }
}

// ---------------- main fused kernel: 256 threads, TMA-fed, ldmatrix A
__global__ void __launch_bounds__(THREADS, 1)
lora_gemm(const float* __restrict__ x, const int* __restrict__ lora_id,
          const float* __restrict__ Wu, float* __restrict__ out) {
    extern __shared__ char smem[];
    const uint32_t sb = smem_u32(smem);
    const int tid = threadIdx.x, lane = tid & 31, wid = tid >> 5;
    const int bid = blockIdx.x;
    const int ntile = bid % NTILES, mtile = bid / NTILES;
    const int m0 = mtile * BM, nb = ntile * BN;

    const int id = lora_id[m0 >> 12];
    const int idx = (id >= 0) ? ((id >> 2) > 49 ? 49 : (id >> 2)) : 0;
    const float coeff = (id >= 0) ? 1.f : 0.f;

    // stage Wu tile (fp32), 256 float4
    {
        const float4* wusrc = (const float4*)Wu + (size_t)idx * N_TOTAL;
        ((float4*)(smem + OFF_WU))[tid] = wusrc[nb + tid];
    }

    const int gid = lane >> 2, tig = lane & 3;
    const int wr = wid >> 2, wc = wid & 3;   // 2 x 4 warp grid, warp tile 64x64

    const float* wsrc = g_Wfrag + (size_t)ntile * SLICES * 8192;
    const float* wdsrc = g_Wdfrag + (size_t)idx * SLICES * 256;

    // ldmatrix A base: lanes 0-7 rows0-7 w0 | 8-15 rows8-15 w0 | 16-23 rows0-7 w1 | 24-31 rows8-15 w1
    const uint32_t abase0 = sb + OFF_A + (wr * 64 + (lane & 15)) * 144 + (lane >> 4) * 16;
    const uint32_t bbase0 = sb + OFF_B + wc * 8192 * 4 / 4;  // wc*8192 bytes? see below
    const uint32_t bcons = sb + OFF_B + wc * 8192 + (lane << 4);
    const uint32_t b2cons = sb + OFF_B2 + lane * 8;
    (void)bbase0;

    float acc[4][8][4];
    float accL[4][4];
    #pragma unroll
    for (int a = 0; a < 4; ++a) {
        #pragma unroll
        for (int b = 0; b < 8; ++b)
            acc[a][b][0] = acc[a][b][1] = acc[a][b][2] = acc[a][b][3] = 0.f;
        accL[a][0] = accL[a][1] = accL[a][2] = accL[a][3] = 0.f;
    }

    if (tid == 0) {
        MBAR_INIT(sb + OFF_BAR + 0, 1);
        MBAR_INIT(sb + OFF_BAR + 8, 1);
        MBAR_INIT(sb + OFF_BAR + 16, 1);
        MBAR_EXPECT(sb + OFF_BAR + 0, TX_BYTES);
        MBAR_EXPECT(sb + OFF_BAR + 8, TX_BYTES);
    }
    __syncthreads();

    // issue copies for (slice, stage): warp w lane0 copies A rows w*16..+15;
    // warp 6 adds B, warp 5 adds B2.
    auto issue = [&](int slice, int st) {
        if (lane == 0) {
            uint32_t mb = sb + OFF_BAR + 8 * st;
            const float* xs = x + (size_t)(m0 + wid * 16) * K_TOTAL + slice * 32;
            uint32_t ad = sb + OFF_A + st * A_STG + (wid * 16) * 144;
            #pragma unroll
            for (int r = 0; r < 16; ++r)
                bulk_cp(ad + r * 144, xs + (size_t)r * K_TOTAL, 128, mb);
            if (wid == 6) bulk_cp(sb + OFF_B + st * B_STG, wsrc + (size_t)slice * 8192, 32768, mb);
            if (wid == 5) bulk_cp(sb + OFF_B2 + st * B2_STG, wdsrc + slice * 256, 1024, mb);
        }
    };
    issue(0, 0);
    issue(1, 1);

    // ---- main loop over 32-k slices, 3-stage pipeline
    #pragma unroll 1
    for (int s = 0; s < SLICES; ++s) {
        const int st = s % 3;
        MBAR_WAIT(sb + OFF_BAR + 8 * st, (s / 3) & 1);

        const uint32_t ab = abase0 + st * A_STG;
        const uint32_t bb = bcons + st * B_STG;
        const uint32_t b2 = b2cons + st * B2_STG;
        #pragma unroll
        for (int ksl = 0; ksl < 4; ++ksl) {
            uint32_t a[4][4];
            #pragma unroll
            for (int mf = 0; mf < 4; ++mf) {
                asm volatile("ldmatrix.sync.aligned.m8n8.x4.shared.b16 {%0,%1,%2,%3}, [%4];"
                             : "=r"(a[mf][0]), "=r"(a[mf][1]), "=r"(a[mf][2]), "=r"(a[mf][3])
                             : "r"(ab + mf * 16 * 144 + ksl * 32));
                #pragma unroll
                for (int q = 0; q < 4; ++q)
                    asm("cvt.rna.tf32.f32 %0, %0;" : "+r"(a[mf][q]));
            }
            #pragma unroll
            for (int nfp = 0; nfp < 4; ++nfp) {
                uint32_t b[4];
                asm volatile("ld.shared.v4.b32 {%0,%1,%2,%3}, [%4];"
                             : "=r"(b[0]), "=r"(b[1]), "=r"(b[2]), "=r"(b[3])
                             : "r"(bb + (((nfp * 4 + ksl) * 32) << 4)));
                #pragma unroll
                for (int mf = 0; mf < 4; ++mf) {
                    mma8(acc[mf][2 * nfp], a[mf], b[0], b[1]);
                    mma8(acc[mf][2 * nfp + 1], a[mf], b[2], b[3]);
                }
            }
            if (wc == 0) {
                uint32_t bl[2];
                asm volatile("ld.shared.v2.b32 {%0,%1}, [%2];"
                             : "=r"(bl[0]), "=r"(bl[1]) : "r"(b2 + ksl * 256));
                #pragma unroll
                for (int mf = 0; mf < 4; ++mf) mma8(accL[mf], a[mf], bl[0], bl[1]);
            }
        }

        if (s + 2 < SLICES && tid == 0)
            MBAR_EXPECT(sb + OFF_BAR + 8 * ((s + 2) % 3), TX_BYTES);
        __syncthreads();
        if (s + 2 < SLICES) issue(s + 2, (s + 2) % 3);
    }

    // ---- epilogue: stage lora-down, fused add + store (R6 layout)
    float* dns = (float*)(smem + OFF_DN);
    if (wc == 0 && tig < 2) {
        #pragma unroll
        for (int mf = 0; mf < 4; ++mf) {
            int mlo = wr * 64 + mf * 16 + gid, mhi = mlo + 8;
            dns[mlo * 4 + 2 * tig] = accL[mf][0] * coeff;
            dns[mlo * 4 + 2 * tig + 1] = accL[mf][1] * coeff;
            dns[mhi * 4 + 2 * tig] = accL[mf][2] * coeff;
            dns[mhi * 4 + 2 * tig + 1] = accL[mf][3] * coeff;
        }
    }
    __syncthreads();

    const float4* wus = (const float4*)(smem + OFF_WU);
    #pragma unroll
    for (int mf = 0; mf < 4; ++mf) {
        int mlo = wr * 64 + mf * 16 + gid, mhi = mlo + 8;
        float4 dlo = ((const float4*)dns)[mlo];
        float4 dhi = ((const float4*)dns)[mhi];
        float* olo = out + (size_t)(m0 + mlo) * N_TOTAL + nb;
        float* ohi = out + (size_t)(m0 + mhi) * N_TOTAL + nb;
        #pragma unroll
        for (int nf = 0; nf < 8; ++nf) {
            int n = wc * 64 + nf * 8 + 2 * tig;
            float4 w0 = wus[n], w1 = wus[n + 1];
            float2 vlo, vhi;
            vlo.x = acc[mf][nf][0] + dlo.x * w0.x + dlo.y * w0.y + dlo.z * w0.z + dlo.w * w0.w;
            vlo.y = acc[mf][nf][1] + dlo.x * w1.x + dlo.y * w1.y + dlo.z * w1.z + dlo.w * w1.w;
            vhi.x = acc[mf][nf][2] + dhi.x * w0.x + dhi.y * w0.y + dhi.z * w0.z + dhi.w * w0.w;
            vhi.y = acc[mf][nf][3] + dhi.x * w1.x + dhi.y * w1.y + dhi.z * w1.z + dhi.w * w1.w;
            *(float2*)(olo + n) = vlo;
            *(float2*)(ohi + n) = vhi;
        }
    }
}

extern "C" void kernel_launch(void* const* d_in, const int* in_sizes, int n_in,
                              void* d_out, int out_size) {
    const float* x = (const float*)d_in[0];
    const int* lid = (const int*)d_in[1];
    const float* W = (const float*)d_in[2];
    const float* Wd = (const float*)d_in[3];
    const float* Wu = (const float*)d_in[4];
    float* out = (float*)d_out;

    cudaFuncSetAttribute(lora_gemm, cudaFuncAttributeMaxDynamicSharedMemorySize, SMEM_BYTES);
    int total = N_TOTAL * K_TOTAL + 50 * K_TOTAL * 8;
    prep_kernel<<<(total + 255) / 256, 256>>>(W, Wd);
    lora_gemm<<<GRID, THREADS, SMEM_BYTES>>>(x, lid, Wu, out);
}

// round 9
// speedup vs baseline: 1.7015x; 1.0841x over previous
#include <cuda_runtime.h>
#include <cstdint>

static constexpr int K_TOTAL = 1280, N_TOTAL = 1280;
static constexpr int BM = 128, BN = 256;
static constexpr int SLICES = 40;              // 32-k slices
static constexpr int NTILES = 5, MTILES = 512;
static constexpr int GRID = NTILES * MTILES;   // 2560
static constexpr int THREADS = 256;
static constexpr int STAGES = 4;

// smem layout (bytes), 4 stages
static constexpr int A_STG = 18432;   // 128 rows * 144B
static constexpr int B_STG = 32768;
static constexpr int B2_STG = 1024;
static constexpr int OFF_A = 0;                 // 4*18432 = 73728
static constexpr int OFF_B = 73728;             // 4*32768 = 131072
static constexpr int OFF_B2 = 204800;           // 4*1024 = 4096
static constexpr int OFF_WU = 208896;           // 4096
static constexpr int OFF_DN = 212992;           // 2048
static constexpr int OFF_BAR = 215040;          // 4 mbarriers
static constexpr int SMEM_BYTES = 215552;
static constexpr unsigned TX_BYTES = 16384u + 32768u + 1024u;

// W fragments, per 32-k slice block of 8192 floats:
// ((((wc*4+nfp)*4+ks)*32 + gid*4 + tig)*4 + nfo*2 + kh)
__device__ __align__(16) float g_Wfrag[NTILES * SLICES * 8192];
// Wd fragments: [lora][slice32][(ks*32+lane)*2 + kh]
__device__ __align__(16) float g_Wdfrag[50 * SLICES * 256];

__device__ __forceinline__ uint32_t smem_u32(const void* p) {
    uint32_t a;
    asm("{ .reg .u64 t; cvta.to.shared.u64 t, %1; cvt.u32.u64 %0, t; }" : "=r"(a) : "l"(p));
    return a;
}
__device__ __forceinline__ uint32_t rna(float f) {
    uint32_t b;
    asm("cvt.rna.tf32.f32 %0, %1;" : "=r"(b) : "f"(f));
    return b;
}
__device__ __forceinline__ void mma8(float* c, const uint32_t* a, uint32_t b0, uint32_t b1) {
    asm volatile(
        "mma.sync.aligned.m16n8k8.row.col.f32.tf32.tf32.f32 "
        "{%0,%1,%2,%3}, {%4,%5,%6,%7}, {%8,%9}, {%0,%1,%2,%3};"
        : "+f"(c[0]), "+f"(c[1]), "+f"(c[2]), "+f"(c[3])
        : "r"(a[0]), "r"(a[1]), "r"(a[2]), "r"(a[3]), "r"(b0), "r"(b1));
}
__device__ __forceinline__ void bulk_cp(uint32_t dst, const void* src, uint32_t bytes, uint32_t mb) {
    asm volatile(
        "cp.async.bulk.shared::cta.global.mbarrier::complete_tx::bytes [%0], [%1], %2, [%3];"
        :: "r"(dst), "l"(src), "r"(bytes), "r"(mb) : "memory");
}
#define MBAR_INIT(a, c) \
    asm volatile("mbarrier.init.shared.b64 [%0], %1;" :: "r"((uint32_t)(a)), "r"((uint32_t)(c)) : "memory")
#define MBAR_EXPECT(a, tx) \
    asm volatile("mbarrier.arrive.expect_tx.shared.b64 _, [%0], %1;" :: "r"((uint32_t)(a)), "r"((uint32_t)(tx)) : "memory")
#define MBAR_WAIT(a, ph) do { \
    uint32_t _m = (uint32_t)(a), _p = (uint32_t)(ph), _d; \
    asm volatile("{ .reg .pred p; mbarrier.try_wait.parity.acquire.cta.shared::cta.b64 p, [%1], %2; selp.b32 %0, 1, 0, p; }" \
        : "=r"(_d) : "r"(_m), "r"(_p) : "memory"); \
    if (!_d) { \
        asm volatile("{ .reg .pred P1;\nWL_%=: mbarrier.try_wait.parity.acquire.cta.shared::cta.b64 P1, [%0], %1, 0x989680;\n@P1 bra.uni WD_%=;\nbra.uni WL_%=;\nWD_%=: }" \
            :: "r"(_m), "r"(_p) : "memory"); \
    } \
} while (0)

// ---------------- prepass (fragment layout unchanged)
__global__ void prep_kernel(const float* __restrict__ W, const float* __restrict__ Wd) {
    int i = blockIdx.x * blockDim.x + threadIdx.x;
    const int NW = N_TOTAL * K_TOTAL;
    if (i < NW) {
        int n = i / K_TOTAL, k = i % K_TOTAL;
        int ntile = n >> 8, nn = n & 255;
        int wc = nn >> 6, nf = (nn >> 3) & 7, gid = nn & 7;
        int nfp = nf >> 1, nfo = nf & 1;
        int slice = k >> 5, ks = (k >> 3) & 3, kh = (k >> 2) & 1, tig = k & 3;
        int off = (ntile * SLICES + slice) * 8192 +
                  ((((wc * 4 + nfp) * 4 + ks) * 32 + gid * 4 + tig) * 4 + nfo * 2 + kh);
        g_Wfrag[off] = __uint_as_float(rna(W[i]));
    } else if (i < NW + 50 * K_TOTAL * 8) {
        int j = i - NW;
        int gid = j & 7, t = j >> 3, k = t % K_TOTAL, l = t / K_TOTAL;
        float v = 0.f;
        if (gid < 4) v = __uint_as_float(rna(Wd[(l * 4 + gid) * K_TOTAL + k]));
        int slice = k >> 5, ks = (k >> 3) & 3, kh = (k >> 2) & 1, tig = k & 3;
        g_Wdfrag[(l * SLICES + slice) * 256 + (ks * 32 + gid * 4 + tig) * 2 + kh] = v;
    }
}

// ---------------- main fused kernel: bulk-async fed, ldmatrix A, no inner cvt
__global__ void __launch_bounds__(THREADS, 1)
lora_gemm(const float* __restrict__ x, const int* __restrict__ lora_id,
          const float* __restrict__ Wu, float* __restrict__ out) {
    extern __shared__ char smem[];
    const uint32_t sb = smem_u32(smem);
    const int tid = threadIdx.x, lane = tid & 31, wid = tid >> 5;
    const int bid = blockIdx.x;
    const int ntile = bid % NTILES, mtile = bid / NTILES;
    const int m0 = mtile * BM, nb = ntile * BN;

    const int id = lora_id[m0 >> 12];
    const int idx = (id >= 0) ? ((id >> 2) > 49 ? 49 : (id >> 2)) : 0;
    const float coeff = (id >= 0) ? 1.f : 0.f;

    // stage Wu tile (fp32), 256 float4
    {
        const float4* wusrc = (const float4*)Wu + (size_t)idx * N_TOTAL;
        ((float4*)(smem + OFF_WU))[tid] = wusrc[nb + tid];
    }

    const int gid = lane >> 2, tig = lane & 3;
    const int wr = wid >> 2, wc = wid & 3;   // 2 x 4 warp grid, warp tile 64x64

    const float* wsrc = g_Wfrag + (size_t)ntile * SLICES * 8192;
    const float* wdsrc = g_Wdfrag + (size_t)idx * SLICES * 256;

    const uint32_t abase0 = sb + OFF_A + (wr * 64 + (lane & 15)) * 144 + (lane >> 4) * 16;
    const uint32_t bcons = sb + OFF_B + wc * 8192 + (lane << 4);
    const uint32_t b2cons = sb + OFF_B2 + lane * 8;

    float acc[4][8][4];
    float accL[4][4];
    #pragma unroll
    for (int a = 0; a < 4; ++a) {
        #pragma unroll
        for (int b = 0; b < 8; ++b)
            acc[a][b][0] = acc[a][b][1] = acc[a][b][2] = acc[a][b][3] = 0.f;
        accL[a][0] = accL[a][1] = accL[a][2] = accL[a][3] = 0.f;
    }

    if (tid == 0) {
        #pragma unroll
        for (int st = 0; st < STAGES; ++st) MBAR_INIT(sb + OFF_BAR + 8 * st, 1);
        MBAR_EXPECT(sb + OFF_BAR + 0, TX_BYTES);
        MBAR_EXPECT(sb + OFF_BAR + 8, TX_BYTES);
        MBAR_EXPECT(sb + OFF_BAR + 16, TX_BYTES);
    }
    __syncthreads();

    auto issue = [&](int slice, int st) {
        if (lane == 0) {
            uint32_t mb = sb + OFF_BAR + 8 * st;
            const float* xs = x + (size_t)(m0 + wid * 16) * K_TOTAL + slice * 32;
            uint32_t ad = sb + OFF_A + st * A_STG + (wid * 16) * 144;
            #pragma unroll
            for (int r = 0; r < 16; ++r)
                bulk_cp(ad + r * 144, xs + (size_t)r * K_TOTAL, 128, mb);
            if (wid == 6) bulk_cp(sb + OFF_B + st * B_STG, wsrc + (size_t)slice * 8192, 32768, mb);
            if (wid == 5) bulk_cp(sb + OFF_B2 + st * B2_STG, wdsrc + slice * 256, 1024, mb);
        }
    };
    issue(0, 0);
    issue(1, 1);
    issue(2, 2);

    // ---- main loop over 32-k slices, 4-stage pipeline
    #pragma unroll 1
    for (int s = 0; s < SLICES; ++s) {
        const int st = s & 3;
        MBAR_WAIT(sb + OFF_BAR + 8 * st, (s >> 2) & 1);

        const uint32_t ab = abase0 + st * A_STG;
        const uint32_t bb = bcons + st * B_STG;
        const uint32_t b2 = b2cons + st * B2_STG;
        #pragma unroll
        for (int ksl = 0; ksl < 4; ++ksl) {
            uint32_t a[4][4];
            #pragma unroll
            for (int mf = 0; mf < 4; ++mf)
                asm volatile("ldmatrix.sync.aligned.m8n8.x4.shared.b16 {%0,%1,%2,%3}, [%4];"
                             : "=r"(a[mf][0]), "=r"(a[mf][1]), "=r"(a[mf][2]), "=r"(a[mf][3])
                             : "r"(ab + mf * 16 * 144 + ksl * 32));
            #pragma unroll
            for (int nfp = 0; nfp < 4; ++nfp) {
                uint32_t b[4];
                asm volatile("ld.shared.v4.b32 {%0,%1,%2,%3}, [%4];"
                             : "=r"(b[0]), "=r"(b[1]), "=r"(b[2]), "=r"(b[3])
                             : "r"(bb + (((nfp * 4 + ksl) * 32) << 4)));
                #pragma unroll
                for (int mf = 0; mf < 4; ++mf) {
                    mma8(acc[mf][2 * nfp], a[mf], b[0], b[1]);
                    mma8(acc[mf][2 * nfp + 1], a[mf], b[2], b[3]);
                }
            }
            if (wc == 0) {
                uint32_t bl[2];
                asm volatile("ld.shared.v2.b32 {%0,%1}, [%2];"
                             : "=r"(bl[0]), "=r"(bl[1]) : "r"(b2 + ksl * 256));
                #pragma unroll
                for (int mf = 0; mf < 4; ++mf) mma8(accL[mf], a[mf], bl[0], bl[1]);
            }
        }

        if (s + 3 < SLICES && tid == 0)
            MBAR_EXPECT(sb + OFF_BAR + 8 * ((s + 3) & 3), TX_BYTES);
        __syncthreads();
        if (s + 3 < SLICES) issue(s + 3, (s + 3) & 3);
    }

    // ---- epilogue: stage lora-down, fused add + store
    float* dns = (float*)(smem + OFF_DN);
    if (wc == 0 && tig < 2) {
        #pragma unroll
        for (int mf = 0; mf < 4; ++mf) {
            int mlo = wr * 64 + mf * 16 + gid, mhi = mlo + 8;
            dns[mlo * 4 + 2 * tig] = accL[mf][0] * coeff;
            dns[mlo * 4 + 2 * tig + 1] = accL[mf][1] * coeff;
            dns[mhi * 4 + 2 * tig] = accL[mf][2] * coeff;
            dns[mhi * 4 + 2 * tig + 1] = accL[mf][3] * coeff;
        }
    }
    __syncthreads();

    const float4* wus = (const float4*)(smem + OFF_WU);
    #pragma unroll
    for (int mf = 0; mf < 4; ++mf) {
        int mlo = wr * 64 + mf * 16 + gid, mhi = mlo + 8;
        float4 dlo = ((const float4*)dns)[mlo];
        float4 dhi = ((const float4*)dns)[mhi];
        float* olo = out + (size_t)(m0 + mlo) * N_TOTAL + nb;
        float* ohi = out + (size_t)(m0 + mhi) * N_TOTAL + nb;
        #pragma unroll
        for (int nf = 0; nf < 8; ++nf) {
            int n = wc * 64 + nf * 8 + 2 * tig;
            float4 w0 = wus[n], w1 = wus[n + 1];
            float2 vlo, vhi;
            vlo.x = acc[mf][nf][0] + dlo.x * w0.x + dlo.y * w0.y + dlo.z * w0.z + dlo.w * w0.w;
            vlo.y = acc[mf][nf][1] + dlo.x * w1.x + dlo.y * w1.y + dlo.z * w1.z + dlo.w * w1.w;
            vhi.x = acc[mf][nf][2] + dhi.x * w0.x + dhi.y * w0.y + dhi.z * w0.z + dhi.w * w0.w;
            vhi.y = acc[mf][nf][3] + dhi.x * w1.x + dhi.y * w1.y + dhi.z * w1.z + dhi.w * w1.w;
            *(float2*)(olo + n) = vlo;
            *(float2*)(ohi + n) = vhi;
        }
    }
}

extern "C" void kernel_launch(void* const* d_in, const int* in_sizes, int n_in,
                              void* d_out, int out_size) {
    const float* x = (const float*)d_in[0];
    const int* lid = (const int*)d_in[1];
    const float* W = (const float*)d_in[2];
    const float* Wd = (const float*)d_in[3];
    const float* Wu = (const float*)d_in[4];
    float* out = (float*)d_out;

    cudaFuncSetAttribute(lora_gemm, cudaFuncAttributeMaxDynamicSharedMemorySize, SMEM_BYTES);
    int total = N_TOTAL * K_TOTAL + 50 * K_TOTAL * 8;
    prep_kernel<<<(total + 255) / 256, 256>>>(W, Wd);
    lora_gemm<<<GRID, THREADS, SMEM_BYTES>>>(x, lid, Wu, out);
}

// round 10
// speedup vs baseline: 1.9899x; 1.1695x over previous
#include <cuda_runtime.h>
#include <cstdint>

static constexpr int K_TOTAL = 1280, N_TOTAL = 1280;
static constexpr int BM = 128, BN = 256;
static constexpr int SLICES = 40;              // 32-k slices
static constexpr int NTILES = 5, MTILES = 512;
static constexpr int GRID = NTILES * MTILES;   // 2560
static constexpr int THREADS = 512;
static constexpr int STAGES = 4;

// smem layout (bytes), 4 stages
static constexpr int A_STG = 18432;   // 128 rows * 144B
static constexpr int B_STG = 32768;
static constexpr int B2_STG = 1024;
static constexpr int OFF_A = 0;
static constexpr int OFF_B = 73728;
static constexpr int OFF_B2 = 204800;
static constexpr int OFF_WU = 208896;
static constexpr int OFF_DN = 212992;
static constexpr int OFF_BAR = 215040;
static constexpr int SMEM_BYTES = 215552;
static constexpr unsigned TX_BYTES = 16384u + 32768u + 1024u;

// W fragments, per 32-k slice block of 8192 floats:
// (((pair*4+ks)*32 + gid*4 + tig)*4 + nfo*2 + kh), pair = n16-group 0..15
__device__ __align__(16) float g_Wfrag[NTILES * SLICES * 8192];
// Wd fragments: [lora][slice32][(ks*32+lane)*2 + kh]
__device__ __align__(16) float g_Wdfrag[50 * SLICES * 256];

__device__ __forceinline__ uint32_t smem_u32(const void* p) {
    uint32_t a;
    asm("{ .reg .u64 t; cvta.to.shared.u64 t, %1; cvt.u32.u64 %0, t; }" : "=r"(a) : "l"(p));
    return a;
}
__device__ __forceinline__ uint32_t rna(float f) {
    uint32_t b;
    asm("cvt.rna.tf32.f32 %0, %1;" : "=r"(b) : "f"(f));
    return b;
}
__device__ __forceinline__ void mma8(float* c, const uint32_t* a, uint32_t b0, uint32_t b1) {
    asm volatile(
        "mma.sync.aligned.m16n8k8.row.col.f32.tf32.tf32.f32 "
        "{%0,%1,%2,%3}, {%4,%5,%6,%7}, {%8,%9}, {%0,%1,%2,%3};"
        : "+f"(c[0]), "+f"(c[1]), "+f"(c[2]), "+f"(c[3])
        : "r"(a[0]), "r"(a[1]), "r"(a[2]), "r"(a[3]), "r"(b0), "r"(b1));
}
__device__ __forceinline__ void bulk_cp(uint32_t dst, const void* src, uint32_t bytes, uint32_t mb) {
    asm volatile(
        "cp.async.bulk.shared::cta.global.mbarrier::complete_tx::bytes [%0], [%1], %2, [%3];"
        :: "r"(dst), "l"(src), "r"(bytes), "r"(mb) : "memory");
}
#define MBAR_INIT(a, c) \
    asm volatile("mbarrier.init.shared.b64 [%0], %1;" :: "r"((uint32_t)(a)), "r"((uint32_t)(c)) : "memory")
#define MBAR_EXPECT(a, tx) \
    asm volatile("mbarrier.arrive.expect_tx.shared.b64 _, [%0], %1;" :: "r"((uint32_t)(a)), "r"((uint32_t)(tx)) : "memory")
#define MBAR_WAIT(a, ph) do { \
    uint32_t _m = (uint32_t)(a), _p = (uint32_t)(ph), _d; \
    asm volatile("{ .reg .pred p; mbarrier.try_wait.parity.acquire.cta.shared::cta.b64 p, [%1], %2; selp.b32 %0, 1, 0, p; }" \
        : "=r"(_d) : "r"(_m), "r"(_p) : "memory"); \
    if (!_d) { \
        asm volatile("{ .reg .pred P1;\nWL_%=: mbarrier.try_wait.parity.acquire.cta.shared::cta.b64 P1, [%0], %1, 0x989680;\n@P1 bra.uni WD_%=;\nbra.uni WL_%=;\nWD_%=: }" \
            :: "r"(_m), "r"(_p) : "memory"); \
    } \
} while (0)

// ---------------- prepass (same fragment convention; pair = wc*4+nfp of R9)
__global__ void prep_kernel(const float* __restrict__ W, const float* __restrict__ Wd) {
    int i = blockIdx.x * blockDim.x + threadIdx.x;
    const int NW = N_TOTAL * K_TOTAL;
    if (i < NW) {
        int n = i / K_TOTAL, k = i % K_TOTAL;
        int ntile = n >> 8, nn = n & 255;
        int pair = nn >> 4, nfo = (nn >> 3) & 1, gid = nn & 7;
        int slice = k >> 5, ks = (k >> 3) & 3, kh = (k >> 2) & 1, tig = k & 3;
        int off = (ntile * SLICES + slice) * 8192 +
                  (((pair * 4 + ks) * 32 + gid * 4 + tig) * 4 + nfo * 2 + kh);
        g_Wfrag[off] = __uint_as_float(rna(W[i]));
    } else if (i < NW + 50 * K_TOTAL * 8) {
        int j = i - NW;
        int gid = j & 7, t = j >> 3, k = t % K_TOTAL, l = t / K_TOTAL;
        float v = 0.f;
        if (gid < 4) v = __uint_as_float(rna(Wd[(l * 4 + gid) * K_TOTAL + k]));
        int slice = k >> 5, ks = (k >> 3) & 3, kh = (k >> 2) & 1, tig = k & 3;
        g_Wdfrag[(l * SLICES + slice) * 256 + (ks * 32 + gid * 4 + tig) * 2 + kh] = v;
    }
}

// ---------------- main fused kernel: 512 threads, warp tile 64x32, TMA-fed
__global__ void __launch_bounds__(THREADS, 1)
lora_gemm(const float* __restrict__ x, const int* __restrict__ lora_id,
          const float* __restrict__ Wu, float* __restrict__ out) {
    extern __shared__ char smem[];
    const uint32_t sb = smem_u32(smem);
    const int tid = threadIdx.x, lane = tid & 31, wid = tid >> 5;
    const int bid = blockIdx.x;
    const int ntile = bid % NTILES, mtile = bid / NTILES;
    const int m0 = mtile * BM, nb = ntile * BN;

    const int id = lora_id[m0 >> 12];
    const int idx = (id >= 0) ? ((id >> 2) > 49 ? 49 : (id >> 2)) : 0;
    const float coeff = (id >= 0) ? 1.f : 0.f;

    if (tid < 256) {
        const float4* wusrc = (const float4*)Wu + (size_t)idx * N_TOTAL;
        ((float4*)(smem + OFF_WU))[tid] = wusrc[nb + tid];
    }

    const int gid = lane >> 2, tig = lane & 3;
    const int wr = wid >> 3, wc = wid & 7;   // 2 x 8 warp grid, warp tile 64x32

    const float* wsrc = g_Wfrag + (size_t)ntile * SLICES * 8192;
    const float* wdsrc = g_Wdfrag + (size_t)idx * SLICES * 256;

    const uint32_t abase0 = sb + OFF_A + (wr * 64 + (lane & 15)) * 144 + (lane >> 4) * 16;
    const uint32_t bcons = sb + OFF_B + wc * 4096 + (lane << 4);
    const uint32_t b2cons = sb + OFF_B2 + lane * 8;

    float acc[4][4][4];
    float accL[4][4];
    #pragma unroll
    for (int a = 0; a < 4; ++a) {
        #pragma unroll
        for (int b = 0; b < 4; ++b)
            acc[a][b][0] = acc[a][b][1] = acc[a][b][2] = acc[a][b][3] = 0.f;
        accL[a][0] = accL[a][1] = accL[a][2] = accL[a][3] = 0.f;
    }

    if (tid == 0) {
        #pragma unroll
        for (int st = 0; st < STAGES; ++st) MBAR_INIT(sb + OFF_BAR + 8 * st, 1);
        MBAR_EXPECT(sb + OFF_BAR + 0, TX_BYTES);
        MBAR_EXPECT(sb + OFF_BAR + 8, TX_BYTES);
        MBAR_EXPECT(sb + OFF_BAR + 16, TX_BYTES);
    }
    __syncthreads();

    auto issue = [&](int slice, int st) {
        if (lane == 0 && wid < 8) {
            uint32_t mb = sb + OFF_BAR + 8 * st;
            const float* xs = x + (size_t)(m0 + wid * 16) * K_TOTAL + slice * 32;
            uint32_t ad = sb + OFF_A + st * A_STG + (wid * 16) * 144;
            #pragma unroll
            for (int r = 0; r < 16; ++r)
                bulk_cp(ad + r * 144, xs + (size_t)r * K_TOTAL, 128, mb);
            if (wid == 6) bulk_cp(sb + OFF_B + st * B_STG, wsrc + (size_t)slice * 8192, 32768, mb);
            if (wid == 5) bulk_cp(sb + OFF_B2 + st * B2_STG, wdsrc + slice * 256, 1024, mb);
        }
    };
    issue(0, 0);
    issue(1, 1);
    issue(2, 2);

    // ---- main loop over 32-k slices, 4-stage pipeline
    #pragma unroll 1
    for (int s = 0; s < SLICES; ++s) {
        const int st = s & 3;
        MBAR_WAIT(sb + OFF_BAR + 8 * st, (s >> 2) & 1);

        const uint32_t ab = abase0 + st * A_STG;
        const uint32_t bb = bcons + st * B_STG;
        const uint32_t b2 = b2cons + st * B2_STG;
        #pragma unroll
        for (int ksl = 0; ksl < 4; ++ksl) {
            uint32_t a[4][4];
            #pragma unroll
            for (int mf = 0; mf < 4; ++mf)
                asm volatile("ldmatrix.sync.aligned.m8n8.x4.shared.b16 {%0,%1,%2,%3}, [%4];"
                             : "=r"(a[mf][0]), "=r"(a[mf][1]), "=r"(a[mf][2]), "=r"(a[mf][3])
                             : "r"(ab + mf * 16 * 144 + ksl * 32));
            #pragma unroll
            for (int nfp = 0; nfp < 2; ++nfp) {
                uint32_t b[4];
                asm volatile("ld.shared.v4.b32 {%0,%1,%2,%3}, [%4];"
                             : "=r"(b[0]), "=r"(b[1]), "=r"(b[2]), "=r"(b[3])
                             : "r"(bb + (((nfp * 4 + ksl) * 32) << 4)));
                #pragma unroll
                for (int mf = 0; mf < 4; ++mf) {
                    mma8(acc[mf][2 * nfp], a[mf], b[0], b[1]);
                    mma8(acc[mf][2 * nfp + 1], a[mf], b[2], b[3]);
                }
            }
            if (wc == 0) {
                uint32_t bl[2];
                asm volatile("ld.shared.v2.b32 {%0,%1}, [%2];"
                             : "=r"(bl[0]), "=r"(bl[1]) : "r"(b2 + ksl * 256));
                #pragma unroll
                for (int mf = 0; mf < 4; ++mf) mma8(accL[mf], a[mf], bl[0], bl[1]);
            }
        }

        if (s + 3 < SLICES && tid == 0)
            MBAR_EXPECT(sb + OFF_BAR + 8 * ((s + 3) & 3), TX_BYTES);
        __syncthreads();
        if (s + 3 < SLICES) issue(s + 3, (s + 3) & 3);
    }

    // ---- epilogue: stage lora-down, fused add + store
    float* dns = (float*)(smem + OFF_DN);
    if (wc == 0 && tig < 2) {
        #pragma unroll
        for (int mf = 0; mf < 4; ++mf) {
            int mlo = wr * 64 + mf * 16 + gid, mhi = mlo + 8;
            dns[mlo * 4 + 2 * tig] = accL[mf][0] * coeff;
            dns[mlo * 4 + 2 * tig + 1] = accL[mf][1] * coeff;
            dns[mhi * 4 + 2 * tig] = accL[mf][2] * coeff;
            dns[mhi * 4 + 2 * tig + 1] = accL[mf][3] * coeff;
        }
    }
    __syncthreads();

    const float4* wus = (const float4*)(smem + OFF_WU);
    #pragma unroll
    for (int mf = 0; mf < 4; ++mf) {
        int mlo = wr * 64 + mf * 16 + gid, mhi = mlo + 8;
        float4 dlo = ((const float4*)dns)[mlo];
        float4 dhi = ((const float4*)dns)[mhi];
        float* olo = out + (size_t)(m0 + mlo) * N_TOTAL + nb;
        float* ohi = out + (size_t)(m0 + mhi) * N_TOTAL + nb;
        #pragma unroll
        for (int nf = 0; nf < 4; ++nf) {
            int n = wc * 32 + nf * 8 + 2 * tig;
            float4 w0 = wus[n], w1 = wus[n + 1];
            float2 vlo, vhi;
            vlo.x = acc[mf][nf][0] + dlo.x * w0.x + dlo.y * w0.y + dlo.z * w0.z + dlo.w * w0.w;
            vlo.y = acc[mf][nf][1] + dlo.x * w1.x + dlo.y * w1.y + dlo.z * w1.z + dlo.w * w1.w;
            vhi.x = acc[mf][nf][2] + dhi.x * w0.x + dhi.y * w0.y + dhi.z * w0.z + dhi.w * w0.w;
            vhi.y = acc[mf][nf][3] + dhi.x * w1.x + dhi.y * w1.y + dhi.z * w1.z + dhi.w * w1.w;
            *(float2*)(olo + n) = vlo;
            *(float2*)(ohi + n) = vhi;
        }
    }
}

extern "C" void kernel_launch(void* const* d_in, const int* in_sizes, int n_in,
                              void* d_out, int out_size) {
    const float* x = (const float*)d_in[0];
    const int* lid = (const int*)d_in[1];
    const float* W = (const float*)d_in[2];
    const float* Wd = (const float*)d_in[3];
    const float* Wu = (const float*)d_in[4];
    float* out = (float*)d_out;

    cudaFuncSetAttribute(lora_gemm, cudaFuncAttributeMaxDynamicSharedMemorySize, SMEM_BYTES);
    int total = N_TOTAL * K_TOTAL + 50 * K_TOTAL * 8;
    prep_kernel<<<(total + 255) / 256, 256>>>(W, Wd);
    lora_gemm<<<GRID, THREADS, SMEM_BYTES>>>(x, lid, Wu, out);
}